// round 13
// baseline (speedup 1.0000x reference)
#include <cuda_runtime.h>
#include <cuda_fp16.h>
#include <cuda_pipeline.h>
#include <mma.h>
#include <cstdint>

using namespace nvcuda;

#define N_CELLS 8192
#define D_GENE  1024
#define D_EMB   256
#define KCAT    768   // [hi | lo | hi] split concat along K

// ---------------- scratch (device globals; no allocation allowed) ----------------
__device__ __half g_Bcat[(size_t)N_CELLS * KCAT];   // [Eh | Eh | El]   [N,K]
__device__ __half g_Acat[(size_t)N_CELLS * KCAT];   // [Ph | Pl | Ph]   [M,K]
__device__ __half g_B2[(size_t)KCAT * D_EMB];       // [Th ; Tl ; Th]   [K,N]
__device__ __half g_Xh[(size_t)N_CELLS * D_GENE];   // expression fp16  [K,N]
__device__ __half g_Gh[(size_t)D_GENE * D_GENE];    // gene_response    [K,N]
__device__ __half g_gated[(size_t)N_CELLS * N_CELLS]; // gated matrix   128 MB
__device__ __half g_M1h[(size_t)N_CELLS * D_GENE];  // (gated@expr)

// ---------------- conversion kernels (R1 originals, proven) ----------------
__global__ void k_cvt_expr(const float* __restrict__ in) {
    int i = blockIdx.x * blockDim.x + threadIdx.x;
    if (i < N_CELLS * D_GENE) g_Xh[i] = __float2half_rn(in[i]);
}

__global__ void k_cvt_gr(const float* __restrict__ in) {
    int i = blockIdx.x * blockDim.x + threadIdx.x;
    if (i < D_GENE * D_GENE) g_Gh[i] = __float2half_rn(in[i]);
}

__global__ void k_cvt_enc(const float* __restrict__ enc) {
    int i = blockIdx.x * blockDim.x + threadIdx.x;
    if (i >= N_CELLS * D_EMB) return;
    int m = i / D_EMB, c = i % D_EMB;
    float x = enc[i];
    __half h = __float2half_rn(x);
    __half l = __float2half_rn(x - __half2float(h));
    size_t base = (size_t)m * KCAT + c;
    g_Bcat[base]             = h;
    g_Bcat[base + D_EMB]     = h;
    g_Bcat[base + 2 * D_EMB] = l;
}

__global__ void k_cvt_T(const float* __restrict__ T) {
    int i = blockIdx.x * blockDim.x + threadIdx.x;
    if (i >= D_EMB * D_EMB) return;
    int k = i / D_EMB, j = i % D_EMB;
    float x = T[i];
    __half h = __float2half_rn(x);
    __half l = __float2half_rn(x - __half2float(h));
    g_B2[(size_t)k * D_EMB + j]               = h;
    g_B2[(size_t)(k + D_EMB) * D_EMB + j]     = l;
    g_B2[(size_t)(k + 2 * D_EMB) * D_EMB + j] = h;
}

// gate math: spatial = exp(-pd/1e4) = 1 - pd*1e-4 (Taylor, err<5e-9 for pd in [0,1]);
// sigmoid saturates for |v|>10 (err<4.5e-5 < fp16 ulp of gated) -> MUFU on ~3% only.
__device__ __forceinline__ float gate_fn(float pd, float v) {
    float sp = fmaf(pd, -1e-4f, 1.0f);
    float sig;
    if (fabsf(v) < 10.0f)
        sig = __fdividef(1.0f, 1.0f + __expf(-v));
    else
        sig = (v > 0.0f) ? 1.0f : 0.0f;
    return sp * sig;
}

// ---------------- wmma GEMM: CTA 128x256 (8 warps, 64x64 each), k-chunk 16 -------
// cp.async intrinsics double buffer (R12-proven load path) on R6's tile geometry.
//   iter it: wait_prior(0) -> sync -> issue copy(it+1 -> buf^1) -> compute(it, buf)
// MODE 0: P   = Bcat @ B2        (M=8192, N=256,  K=768)   B row-major [K,N]
// MODE 1: S   = Acat @ Bcat^T    (M=8192, N=8192, K=768)   B col-major [N,K]
// MODE 2: M1  = gated @ Xh       (M=8192, N=1024, K=8192)  B row-major [K,N]
// MODE 3: out = M1h @ Gh         (M=8192, N=1024, K=1024)  B row-major [K,N]
template <int MODE>
__global__ __launch_bounds__(256)
void gemm_wmma8(const float* __restrict__ aux, float* __restrict__ outf) {
    constexpr bool B_COL = (MODE == 1);
    constexpr int K    = (MODE <= 1) ? KCAT : (MODE == 2 ? N_CELLS : D_GENE);
    constexpr int NK   = K / 16;
    constexpr int Ndim = (MODE == 0) ? D_EMB : (MODE == 1 ? N_CELLS : D_GENE);
    constexpr int LDA  = 24;                  // A pitch (halves): 16 data + 8 pad

    const __half* __restrict__ A =
        (MODE == 0) ? g_Bcat : (MODE == 1) ? g_Acat : (MODE == 2) ? g_gated : g_M1h;
    const __half* __restrict__ B =
        (MODE == 0) ? g_B2 : (MODE == 1) ? g_Bcat : (MODE == 2) ? g_Xh : g_Gh;

    __shared__ __align__(16) __half As[2][128 * 24];  // 2 x 6144 B
    __shared__ __align__(16) __half Bs[2][6144];      // 2 x 12288 B (col 256x24; row 16x264)
    __shared__ __align__(16) float  epbuf[8][320];    // 10240 B  => 47104 B/CTA

    const int tid  = threadIdx.x;    // 0..255
    const int lane = tid & 31;
    const int w    = tid >> 5;       // 0..7
    const int wm   = w >> 2;         // 0..1 -> m offset wm*64
    const int wn   = w & 3;          // 0..3 -> n offset wn*64
    const size_t gm0 = (size_t)blockIdx.y * 128;
    const size_t gn0 = (size_t)blockIdx.x * 256;

    wmma::fragment<wmma::accumulator, 16, 16, 16, float> acc[4][4];
#pragma unroll
    for (int i = 0; i < 4; i++)
#pragma unroll
        for (int j = 0; j < 4; j++) wmma::fill_fragment(acc[i][j], 0.0f);

    // ---- async stage copy: global -> smem, 16B granules ----
    auto load_stage = [&](int it, int buf) {
        const int k0 = it * 16;
        {   // A: 128 rows x 2 chunks(16B) = 256 ops, 1/thread
            int row = tid >> 1, ch = tid & 1;
            __pipeline_memcpy_async(&As[buf][row * LDA + ch * 8],
                                    A + (gm0 + row) * (size_t)K + k0 + ch * 8, 16);
        }
        if (B_COL) {
#pragma unroll
            for (int j = 0; j < 2; j++) {    // 256 rows x 2 chunks = 512 ops
                int idx = tid + j * 256;
                int row = idx >> 1, ch = idx & 1;
                __pipeline_memcpy_async(&Bs[buf][row * 24 + ch * 8],
                                        B + (gn0 + row) * (size_t)K + k0 + ch * 8, 16);
            }
        } else {
#pragma unroll
            for (int j = 0; j < 2; j++) {    // 16 rows x 32 chunks = 512 ops
                int idx = tid + j * 256;
                int row = idx >> 5, ch = idx & 31;
                __pipeline_memcpy_async(&Bs[buf][row * 264 + ch * 8],
                                        B + (size_t)(k0 + row) * Ndim + gn0 + ch * 8, 16);
            }
        }
        __pipeline_commit();
    };

    load_stage(0, 0);

#pragma unroll 1
    for (int it = 0; it < NK; ++it) {
        const int buf = it & 1;
        __pipeline_wait_prior(0);   // copy into `buf` complete
        __syncthreads();            // visible; reads of buf^1 (iter it-1) done
        if (it + 1 < NK) load_stage(it + 1, buf ^ 1);   // lands under compute(it)

        if constexpr (B_COL) {
            wmma::fragment<wmma::matrix_b, 16, 16, 16, __half, wmma::col_major> b[4];
#pragma unroll
            for (int nt = 0; nt < 4; nt++)
                wmma::load_matrix_sync(b[nt], &Bs[buf][(wn * 64 + nt * 16) * 24], 24);
#pragma unroll
            for (int mt = 0; mt < 4; mt++) {
                wmma::fragment<wmma::matrix_a, 16, 16, 16, __half, wmma::row_major> a;
                wmma::load_matrix_sync(a, &As[buf][(wm * 64 + mt * 16) * LDA], LDA);
#pragma unroll
                for (int nt = 0; nt < 4; nt++)
                    wmma::mma_sync(acc[mt][nt], a, b[nt], acc[mt][nt]);
            }
        } else {
            wmma::fragment<wmma::matrix_b, 16, 16, 16, __half, wmma::row_major> b[4];
#pragma unroll
            for (int nt = 0; nt < 4; nt++)
                wmma::load_matrix_sync(b[nt], &Bs[buf][wn * 64 + nt * 16], 264);
#pragma unroll
            for (int mt = 0; mt < 4; mt++) {
                wmma::fragment<wmma::matrix_a, 16, 16, 16, __half, wmma::row_major> a;
                wmma::load_matrix_sync(a, &As[buf][(wm * 64 + mt * 16) * LDA], LDA);
#pragma unroll
                for (int nt = 0; nt < 4; nt++)
                    wmma::mma_sync(acc[mt][nt], a, b[nt], acc[mt][nt]);
            }
        }
    }

    // ---------------- epilogue (per-warp staging, proven pattern) ----------------
    const int r  = lane >> 1;
    const int cb = (lane & 1) * 8;
#pragma unroll
    for (int mt = 0; mt < 4; mt++) {
        const size_t gr = gm0 + wm * 64 + mt * 16 + r;
#pragma unroll
        for (int nt = 0; nt < 4; nt++) {
            wmma::store_matrix_sync(&epbuf[w][0], acc[mt][nt], 20, wmma::mem_row_major);
            __syncwarp();
            const size_t gc = gn0 + wn * 64 + nt * 16 + cb;
            float v[8];
#pragma unroll
            for (int e = 0; e < 8; e++) v[e] = epbuf[w][r * 20 + cb + e];

            if constexpr (MODE == 0) {
                __half2 hh[4], ll[4];
#pragma unroll
                for (int e = 0; e < 4; e++) {
                    __half h0 = __float2half_rn(v[e * 2]);
                    __half h1 = __float2half_rn(v[e * 2 + 1]);
                    hh[e] = __halves2half2(h0, h1);
                    ll[e] = __halves2half2(
                        __float2half_rn(v[e * 2]     - __half2float(h0)),
                        __float2half_rn(v[e * 2 + 1] - __half2float(h1)));
                }
                size_t base = gr * KCAT + gc;
                *(uint4*)(g_Acat + base)             = *(uint4*)hh;
                *(uint4*)(g_Acat + base + D_EMB)     = *(uint4*)ll;
                *(uint4*)(g_Acat + base + 2 * D_EMB) = *(uint4*)hh;
            } else if constexpr (MODE == 1) {
                const float* prow = aux + gr * (size_t)N_CELLS + gc;
                float4 p0 = __ldcs((const float4*)prow);
                float4 p1 = __ldcs((const float4*)(prow + 4));
                float pv[8] = {p0.x, p0.y, p0.z, p0.w, p1.x, p1.y, p1.z, p1.w};
                __half2 o[4];
#pragma unroll
                for (int e = 0; e < 4; e++) {
                    float s0 = gate_fn(pv[e * 2],     v[e * 2]);
                    float s1 = gate_fn(pv[e * 2 + 1], v[e * 2 + 1]);
                    o[e] = __floats2half2_rn(s0, s1);
                }
                *(uint4*)(g_gated + gr * (size_t)N_CELLS + gc) = *(uint4*)o;
            } else if constexpr (MODE == 2) {
                __half2 o[4];
#pragma unroll
                for (int e = 0; e < 4; e++)
                    o[e] = __floats2half2_rn(v[e * 2], v[e * 2 + 1]);
                *(uint4*)(g_M1h + gr * D_GENE + gc) = *(uint4*)o;
            } else {
                float4 o0 = make_float4(v[0] * (1.0f / 1024.0f), v[1] * (1.0f / 1024.0f),
                                        v[2] * (1.0f / 1024.0f), v[3] * (1.0f / 1024.0f));
                float4 o1 = make_float4(v[4] * (1.0f / 1024.0f), v[5] * (1.0f / 1024.0f),
                                        v[6] * (1.0f / 1024.0f), v[7] * (1.0f / 1024.0f));
                *(float4*)(outf + gr * D_GENE + gc)     = o0;
                *(float4*)(outf + gr * D_GENE + gc + 4) = o1;
            }
            __syncwarp();
        }
    }
}

// ---------------- launch ----------------
extern "C" void kernel_launch(void* const* d_in, const int* in_sizes, int n_in,
                              void* d_out, int out_size) {
    const float* expr = (const float*)d_in[0];
    const float* enc  = (const float*)d_in[1];
    const float* pd   = (const float*)d_in[2];
    const float* T    = (const float*)d_in[3];
    const float* gr   = (const float*)d_in[4];
    float* out = (float*)d_out;

    // Order chosen so the 4th launch (ncu capture slot) is the dominant GEMM1.
    k_cvt_enc<<<(N_CELLS * D_EMB) / 256, 256>>>(enc);
    k_cvt_T<<<(D_EMB * D_EMB) / 256, 256>>>(T);
    gemm_wmma8<0><<<dim3(D_EMB / 256,  N_CELLS / 128), 256>>>(nullptr, nullptr);
    gemm_wmma8<1><<<dim3(N_CELLS / 256, N_CELLS / 128), 256>>>(pd, nullptr);
    k_cvt_expr<<<(N_CELLS * D_GENE) / 256, 256>>>(expr);
    k_cvt_gr<<<(D_GENE * D_GENE) / 256, 256>>>(gr);
    gemm_wmma8<2><<<dim3(D_GENE / 256, N_CELLS / 128), 256>>>(nullptr, nullptr);
    gemm_wmma8<3><<<dim3(D_GENE / 256, N_CELLS / 128), 256>>>(nullptr, out);
}

// round 14
// speedup vs baseline: 1.3393x; 1.3393x over previous
#include <cuda_runtime.h>
#include <cuda_fp16.h>
#include <cuda_pipeline.h>
#include <mma.h>
#include <cstdint>

using namespace nvcuda;

#define N_CELLS 8192
#define D_GENE  1024
#define D_EMB   256
#define KCAT    768   // [hi | lo | hi] split concat along K

// ---------------- scratch (device globals; no allocation allowed) ----------------
__device__ __half g_Bcat[(size_t)N_CELLS * KCAT];   // [Eh | Eh | El]   [N,K]
__device__ __half g_Acat[(size_t)N_CELLS * KCAT];   // [Ph | Pl | Ph]   [M,K]
__device__ __half g_B2[(size_t)KCAT * D_EMB];       // [Th ; Tl ; Th]   [K,N]
__device__ __half g_Xh[(size_t)N_CELLS * D_GENE];   // expression fp16  [K,N]
__device__ __half g_Gh[(size_t)D_GENE * D_GENE];    // gene_response    [K,N]
__device__ __half g_gated[(size_t)N_CELLS * N_CELLS]; // gated matrix   128 MB
__device__ __half g_M1h[(size_t)N_CELLS * D_GENE];  // (gated@expr)

// ---------------- conversion kernels (R1 originals, proven) ----------------
__global__ void k_cvt_expr(const float* __restrict__ in) {
    int i = blockIdx.x * blockDim.x + threadIdx.x;
    if (i < N_CELLS * D_GENE) g_Xh[i] = __float2half_rn(in[i]);
}

__global__ void k_cvt_gr(const float* __restrict__ in) {
    int i = blockIdx.x * blockDim.x + threadIdx.x;
    if (i < D_GENE * D_GENE) g_Gh[i] = __float2half_rn(in[i]);
}

__global__ void k_cvt_enc(const float* __restrict__ enc) {
    int i = blockIdx.x * blockDim.x + threadIdx.x;
    if (i >= N_CELLS * D_EMB) return;
    int m = i / D_EMB, c = i % D_EMB;
    float x = enc[i];
    __half h = __float2half_rn(x);
    __half l = __float2half_rn(x - __half2float(h));
    size_t base = (size_t)m * KCAT + c;
    g_Bcat[base]             = h;
    g_Bcat[base + D_EMB]     = h;
    g_Bcat[base + 2 * D_EMB] = l;
}

__global__ void k_cvt_T(const float* __restrict__ T) {
    int i = blockIdx.x * blockDim.x + threadIdx.x;
    if (i >= D_EMB * D_EMB) return;
    int k = i / D_EMB, j = i % D_EMB;
    float x = T[i];
    __half h = __float2half_rn(x);
    __half l = __float2half_rn(x - __half2float(h));
    g_B2[(size_t)k * D_EMB + j]               = h;
    g_B2[(size_t)(k + D_EMB) * D_EMB + j]     = l;
    g_B2[(size_t)(k + 2 * D_EMB) * D_EMB + j] = h;
}

// gate math: spatial = exp(-pd/1e4) = 1 - pd*1e-4 (Taylor, err<5e-9 for pd in [0,1]);
// sigmoid saturates for |v|>10 (err<4.5e-5 < fp16 ulp of gated) -> MUFU on ~3% only.
__device__ __forceinline__ float gate_fn(float pd, float v) {
    float sp = fmaf(pd, -1e-4f, 1.0f);
    float sig;
    if (fabsf(v) < 10.0f)
        sig = __fdividef(1.0f, 1.0f + __expf(-v));
    else
        sig = (v > 0.0f) ? 1.0f : 0.0f;
    return sp * sig;
}

// ---------------- wmma GEMM: CTA 128x128 (4 warps, 64x64 each), k-chunk 16 -------
// 3-stage cp.async pipeline, wait_prior(1): each copy gets 2 compute phases.
// 128-thread CTAs, ~166 regs -> 3 CTAs/SM (12 warps) co-residency (R12-proven).
//   iter it: wait_prior(1) -> sync -> issue copy(stage it+2) -> compute(stage it)
// MODE 0: P   = Bcat @ B2        (M=8192, N=256,  K=768)   B row-major [K,N]
// MODE 1: S   = Acat @ Bcat^T    (M=8192, N=8192, K=768)   B col-major [N,K]
// MODE 2: M1  = gated @ Xh       (M=8192, N=1024, K=8192)  B row-major [K,N]
// MODE 3: out = M1h @ Gh         (M=8192, N=1024, K=1024)  B row-major [K,N]
template <int MODE>
__global__ void gemm_wmma9(const float* __restrict__ aux, float* __restrict__ outf) {
    constexpr bool B_COL = (MODE == 1);
    constexpr int K    = (MODE <= 1) ? KCAT : (MODE == 2 ? N_CELLS : D_GENE);
    constexpr int NK   = K / 16;
    constexpr int Ndim = (MODE == 0) ? D_EMB : (MODE == 1 ? N_CELLS : D_GENE);
    constexpr int LDA  = 24;                  // A pitch (halves): 16 data + 8 pad

    const __half* __restrict__ A =
        (MODE == 0) ? g_Bcat : (MODE == 1) ? g_Acat : (MODE == 2) ? g_gated : g_M1h;
    const __half* __restrict__ B =
        (MODE == 0) ? g_B2 : (MODE == 1) ? g_Bcat : (MODE == 2) ? g_Xh : g_Gh;

    __shared__ __align__(16) __half As[3][128 * 24];  // 3 x 6144 B
    __shared__ __align__(16) __half Bs[3][3072];      // 3 x 6144 B (col 128x24; row 16x136)
    __shared__ __align__(16) float  epbuf[4][320];    // 5120 B  => 41984 B/CTA

    const int tid  = threadIdx.x;    // 0..127
    const int lane = tid & 31;
    const int w    = tid >> 5;       // 0..3
    const int wm   = w >> 1;         // 0..1 -> m offset wm*64
    const int wn   = w & 1;          // 0..1 -> n offset wn*64
    const size_t gm0 = (size_t)blockIdx.y * 128;
    const size_t gn0 = (size_t)blockIdx.x * 128;

    wmma::fragment<wmma::accumulator, 16, 16, 16, float> acc[4][4];
#pragma unroll
    for (int i = 0; i < 4; i++)
#pragma unroll
        for (int j = 0; j < 4; j++) wmma::fill_fragment(acc[i][j], 0.0f);

    // ---- async stage copy: global -> smem, 16B granules ----
    auto load_stage = [&](int it, int buf) {
        const int k0 = it * 16;
#pragma unroll
        for (int j = 0; j < 2; j++) {        // A: 128 rows x 2 chunks = 256 ops
            int idx = tid + j * 128;
            int row = idx >> 1, ch = idx & 1;
            __pipeline_memcpy_async(&As[buf][row * LDA + ch * 8],
                                    A + (gm0 + row) * (size_t)K + k0 + ch * 8, 16);
        }
        if (B_COL) {
#pragma unroll
            for (int j = 0; j < 2; j++) {    // B: 128 rows x 2 chunks = 256 ops
                int idx = tid + j * 128;
                int row = idx >> 1, ch = idx & 1;
                __pipeline_memcpy_async(&Bs[buf][row * 24 + ch * 8],
                                        B + (gn0 + row) * (size_t)K + k0 + ch * 8, 16);
            }
        } else {
#pragma unroll
            for (int j = 0; j < 2; j++) {    // B: 16 rows x 16 chunks = 256 ops
                int idx = tid + j * 128;
                int row = idx >> 4, ch = idx & 15;
                __pipeline_memcpy_async(&Bs[buf][row * 136 + ch * 8],
                                        B + (size_t)(k0 + row) * Ndim + gn0 + ch * 8, 16);
            }
        }
        __pipeline_commit();
    };

    load_stage(0, 0);
    load_stage(1, 1);

#pragma unroll 1
    for (int it = 0; it < NK; ++it) {
        const int buf = it % 3;
        __pipeline_wait_prior(1);   // stage `it` complete (issued >=2 iters ago)
        __syncthreads();            // visible; all warps done reading the buf we reuse next
        if (it + 2 < NK) load_stage(it + 2, (it + 2) % 3);

        if constexpr (B_COL) {
            wmma::fragment<wmma::matrix_b, 16, 16, 16, __half, wmma::col_major> b[4];
#pragma unroll
            for (int nt = 0; nt < 4; nt++)
                wmma::load_matrix_sync(b[nt], &Bs[buf][(wn * 64 + nt * 16) * 24], 24);
#pragma unroll
            for (int mt = 0; mt < 4; mt++) {
                wmma::fragment<wmma::matrix_a, 16, 16, 16, __half, wmma::row_major> a;
                wmma::load_matrix_sync(a, &As[buf][(wm * 64 + mt * 16) * LDA], LDA);
#pragma unroll
                for (int nt = 0; nt < 4; nt++)
                    wmma::mma_sync(acc[mt][nt], a, b[nt], acc[mt][nt]);
            }
        } else {
            wmma::fragment<wmma::matrix_b, 16, 16, 16, __half, wmma::row_major> b[4];
#pragma unroll
            for (int nt = 0; nt < 4; nt++)
                wmma::load_matrix_sync(b[nt], &Bs[buf][wn * 64 + nt * 16], 136);
#pragma unroll
            for (int mt = 0; mt < 4; mt++) {
                wmma::fragment<wmma::matrix_a, 16, 16, 16, __half, wmma::row_major> a;
                wmma::load_matrix_sync(a, &As[buf][(wm * 64 + mt * 16) * LDA], LDA);
#pragma unroll
                for (int nt = 0; nt < 4; nt++)
                    wmma::mma_sync(acc[mt][nt], a, b[nt], acc[mt][nt]);
            }
        }
    }

    // ---------------- epilogue (per-warp staging, proven pattern) ----------------
    const int r  = lane >> 1;
    const int cb = (lane & 1) * 8;
#pragma unroll
    for (int mt = 0; mt < 4; mt++) {
        const size_t gr = gm0 + wm * 64 + mt * 16 + r;
#pragma unroll
        for (int nt = 0; nt < 4; nt++) {
            wmma::store_matrix_sync(&epbuf[w][0], acc[mt][nt], 20, wmma::mem_row_major);
            __syncwarp();
            const size_t gc = gn0 + wn * 64 + nt * 16 + cb;
            float v[8];
#pragma unroll
            for (int e = 0; e < 8; e++) v[e] = epbuf[w][r * 20 + cb + e];

            if constexpr (MODE == 0) {
                __half2 hh[4], ll[4];
#pragma unroll
                for (int e = 0; e < 4; e++) {
                    __half h0 = __float2half_rn(v[e * 2]);
                    __half h1 = __float2half_rn(v[e * 2 + 1]);
                    hh[e] = __halves2half2(h0, h1);
                    ll[e] = __halves2half2(
                        __float2half_rn(v[e * 2]     - __half2float(h0)),
                        __float2half_rn(v[e * 2 + 1] - __half2float(h1)));
                }
                size_t base = gr * KCAT + gc;
                *(uint4*)(g_Acat + base)             = *(uint4*)hh;
                *(uint4*)(g_Acat + base + D_EMB)     = *(uint4*)ll;
                *(uint4*)(g_Acat + base + 2 * D_EMB) = *(uint4*)hh;
            } else if constexpr (MODE == 1) {
                const float* prow = aux + gr * (size_t)N_CELLS + gc;
                float4 p0 = __ldcs((const float4*)prow);
                float4 p1 = __ldcs((const float4*)(prow + 4));
                float pv[8] = {p0.x, p0.y, p0.z, p0.w, p1.x, p1.y, p1.z, p1.w};
                __half2 o[4];
#pragma unroll
                for (int e = 0; e < 4; e++) {
                    float s0 = gate_fn(pv[e * 2],     v[e * 2]);
                    float s1 = gate_fn(pv[e * 2 + 1], v[e * 2 + 1]);
                    o[e] = __floats2half2_rn(s0, s1);
                }
                *(uint4*)(g_gated + gr * (size_t)N_CELLS + gc) = *(uint4*)o;
            } else if constexpr (MODE == 2) {
                __half2 o[4];
#pragma unroll
                for (int e = 0; e < 4; e++)
                    o[e] = __floats2half2_rn(v[e * 2], v[e * 2 + 1]);
                *(uint4*)(g_M1h + gr * D_GENE + gc) = *(uint4*)o;
            } else {
                float4 o0 = make_float4(v[0] * (1.0f / 1024.0f), v[1] * (1.0f / 1024.0f),
                                        v[2] * (1.0f / 1024.0f), v[3] * (1.0f / 1024.0f));
                float4 o1 = make_float4(v[4] * (1.0f / 1024.0f), v[5] * (1.0f / 1024.0f),
                                        v[6] * (1.0f / 1024.0f), v[7] * (1.0f / 1024.0f));
                *(float4*)(outf + gr * D_GENE + gc)     = o0;
                *(float4*)(outf + gr * D_GENE + gc + 4) = o1;
            }
            __syncwarp();
        }
    }
}

// ---------------- launch ----------------
extern "C" void kernel_launch(void* const* d_in, const int* in_sizes, int n_in,
                              void* d_out, int out_size) {
    const float* expr = (const float*)d_in[0];
    const float* enc  = (const float*)d_in[1];
    const float* pd   = (const float*)d_in[2];
    const float* T    = (const float*)d_in[3];
    const float* gr   = (const float*)d_in[4];
    float* out = (float*)d_out;

    // Order chosen so the 4th launch (ncu capture slot) is the dominant GEMM1.
    k_cvt_enc<<<(N_CELLS * D_EMB) / 256, 256>>>(enc);
    k_cvt_T<<<(D_EMB * D_EMB) / 256, 256>>>(T);
    gemm_wmma9<0><<<dim3(D_EMB / 128,  N_CELLS / 128), 128>>>(nullptr, nullptr);
    gemm_wmma9<1><<<dim3(N_CELLS / 128, N_CELLS / 128), 128>>>(pd, nullptr);
    k_cvt_expr<<<(N_CELLS * D_GENE) / 256, 256>>>(expr);
    k_cvt_gr<<<(D_GENE * D_GENE) / 256, 256>>>(gr);
    gemm_wmma9<2><<<dim3(D_GENE / 128, N_CELLS / 128), 128>>>(nullptr, nullptr);
    gemm_wmma9<3><<<dim3(D_GENE / 128, N_CELLS / 128), 128>>>(nullptr, out);
}

// round 15
// speedup vs baseline: 1.6083x; 1.2009x over previous
#include <cuda_runtime.h>
#include <cuda_fp16.h>
#include <cuda_pipeline.h>
#include <mma.h>
#include <cstdint>

using namespace nvcuda;

#define N_CELLS 8192
#define D_GENE  1024
#define D_EMB   256
#define KCAT    768   // [hi | lo | hi] split concat along K

// ---------------- scratch (device globals; no allocation allowed) ----------------
__device__ __half g_Bcat[(size_t)N_CELLS * KCAT];   // [Eh | Eh | El]   [N,K]
__device__ __half g_Acat[(size_t)N_CELLS * KCAT];   // [Ph | Pl | Ph]   [M,K]
__device__ __half g_B2[(size_t)KCAT * D_EMB];       // [Th ; Tl ; Th]   [K,N]
__device__ __half g_Xh[(size_t)N_CELLS * D_GENE];   // expression fp16  [K,N]
__device__ __half g_Gh[(size_t)D_GENE * D_GENE];    // gene_response    [K,N]
__device__ __half g_gated[(size_t)N_CELLS * N_CELLS]; // gated matrix   128 MB
__device__ __half g_M1h[(size_t)N_CELLS * D_GENE];  // (gated@expr)

// ---------------- conversion kernels (R1 originals, proven) ----------------
__global__ void k_cvt_expr(const float* __restrict__ in) {
    int i = blockIdx.x * blockDim.x + threadIdx.x;
    if (i < N_CELLS * D_GENE) g_Xh[i] = __float2half_rn(in[i]);
}

__global__ void k_cvt_gr(const float* __restrict__ in) {
    int i = blockIdx.x * blockDim.x + threadIdx.x;
    if (i < D_GENE * D_GENE) g_Gh[i] = __float2half_rn(in[i]);
}

__global__ void k_cvt_enc(const float* __restrict__ enc) {
    int i = blockIdx.x * blockDim.x + threadIdx.x;
    if (i >= N_CELLS * D_EMB) return;
    int m = i / D_EMB, c = i % D_EMB;
    float x = enc[i];
    __half h = __float2half_rn(x);
    __half l = __float2half_rn(x - __half2float(h));
    size_t base = (size_t)m * KCAT + c;
    g_Bcat[base]             = h;
    g_Bcat[base + D_EMB]     = h;
    g_Bcat[base + 2 * D_EMB] = l;
}

__global__ void k_cvt_T(const float* __restrict__ T) {
    int i = blockIdx.x * blockDim.x + threadIdx.x;
    if (i >= D_EMB * D_EMB) return;
    int k = i / D_EMB, j = i % D_EMB;
    float x = T[i];
    __half h = __float2half_rn(x);
    __half l = __float2half_rn(x - __half2float(h));
    g_B2[(size_t)k * D_EMB + j]               = h;
    g_B2[(size_t)(k + D_EMB) * D_EMB + j]     = l;
    g_B2[(size_t)(k + 2 * D_EMB) * D_EMB + j] = h;
}

// gate math: spatial = exp(-pd/1e4) = 1 - pd*1e-4 (Taylor, err<5e-9 for pd in [0,1]);
// sigmoid saturates for |v|>10 (err<4.5e-5 < fp16 ulp of gated) -> MUFU on ~3% only.
__device__ __forceinline__ float gate_fn(float pd, float v) {
    float sp = fmaf(pd, -1e-4f, 1.0f);
    float sig;
    if (fabsf(v) < 10.0f)
        sig = __fdividef(1.0f, 1.0f + __expf(-v));
    else
        sig = (v > 0.0f) ? 1.0f : 0.0f;
    return sp * sig;
}

// ---------------- wmma GEMM: CTA 128x128 (4 warps, 64x64 each), k-chunk 32 -------
// R12 geometry + THIRD pipeline stage (dynamic smem), wait_prior(1).
//   iter it: wait_prior(1) [(0) on last] -> sync -> issue copy(it+2) -> compute(it)
// Dyn smem: 3 stages x 20480 B (A 128x40h, B 128x40h|32x136h); epilogue aliases stage 0.
// __launch_bounds__(128,3): reg cap 170 (natural 166) -> 3 CTAs/SM = 12 warps.
// MODE 0: P   = Bcat @ B2        (M=8192, N=256,  K=768)   B row-major [K,N]
// MODE 1: S   = Acat @ Bcat^T    (M=8192, N=8192, K=768)   B col-major [N,K]
// MODE 2: M1  = gated @ Xh       (M=8192, N=1024, K=8192)  B row-major [K,N]
// MODE 3: out = M1h @ Gh         (M=8192, N=1024, K=1024)  B row-major [K,N]
#define STAGE_B 20480
#define DSMEM_B (3 * STAGE_B)   // 61440

template <int MODE>
__global__ __launch_bounds__(128, 3)
void gemm_wmma10(const float* __restrict__ aux, float* __restrict__ outf) {
    constexpr bool B_COL = (MODE == 1);
    constexpr int K    = (MODE <= 1) ? KCAT : (MODE == 2 ? N_CELLS : D_GENE);
    constexpr int NK   = K / 32;
    constexpr int Ndim = (MODE == 0) ? D_EMB : (MODE == 1 ? N_CELLS : D_GENE);
    constexpr int LDA  = 40;                  // A pitch (halves): 32 data + 8 pad

    const __half* __restrict__ A =
        (MODE == 0) ? g_Bcat : (MODE == 1) ? g_Acat : (MODE == 2) ? g_gated : g_M1h;
    const __half* __restrict__ B =
        (MODE == 0) ? g_B2 : (MODE == 1) ? g_Bcat : (MODE == 2) ? g_Xh : g_Gh;

    extern __shared__ __align__(16) char dsm[];
    auto AsP = [&](int buf) { return (__half*)(dsm + buf * STAGE_B); };
    auto BsP = [&](int buf) { return (__half*)(dsm + buf * STAGE_B + 10240); };

    const int tid  = threadIdx.x;    // 0..127
    const int lane = tid & 31;
    const int w    = tid >> 5;       // 0..3
    const int wm   = w >> 1;         // 0..1 -> m offset wm*64
    const int wn   = w & 1;          // 0..1 -> n offset wn*64
    const size_t gm0 = (size_t)blockIdx.y * 128;
    const size_t gn0 = (size_t)blockIdx.x * 128;

    wmma::fragment<wmma::accumulator, 16, 16, 16, float> acc[4][4];
#pragma unroll
    for (int i = 0; i < 4; i++)
#pragma unroll
        for (int j = 0; j < 4; j++) wmma::fill_fragment(acc[i][j], 0.0f);

    // ---- async stage copy: global -> smem, 16B granules (R12-proven path) ----
    auto load_stage = [&](int it, int buf) {
        const int k0 = it * 32;
        __half* sA = AsP(buf);
        __half* sB = BsP(buf);
#pragma unroll
        for (int j = 0; j < 4; j++) {
            int idx = tid + j * 128;
            int row = idx >> 2, ch = idx & 3;    // A: 128 rows x 4 chunks(16B)
            __pipeline_memcpy_async(&sA[row * LDA + ch * 8],
                                    A + (gm0 + row) * (size_t)K + k0 + ch * 8, 16);
        }
        if (B_COL) {
#pragma unroll
            for (int j = 0; j < 4; j++) {
                int idx = tid + j * 128;
                int row = idx >> 2, ch = idx & 3;
                __pipeline_memcpy_async(&sB[row * 40 + ch * 8],
                                        B + (gn0 + row) * (size_t)K + k0 + ch * 8, 16);
            }
        } else {
#pragma unroll
            for (int j = 0; j < 4; j++) {
                int idx = tid + j * 128;
                int row = idx >> 4, ch = idx & 15;   // 32 rows x 16 chunks
                __pipeline_memcpy_async(&sB[row * 136 + ch * 8],
                                        B + (size_t)(k0 + row) * Ndim + gn0 + ch * 8, 16);
            }
        }
        __pipeline_commit();
    };

    load_stage(0, 0);
    if (NK > 1) load_stage(1, 1);

#pragma unroll 1
    for (int it = 0; it < NK; ++it) {
        const int buf = it % 3;
        if (it == NK - 1) __pipeline_wait_prior(0);   // tail: no group behind us
        else              __pipeline_wait_prior(1);   // stage `it` complete
        __syncthreads();   // visible to all; compute(it-1) done before buf-reuse below
        if (it + 2 < NK) load_stage(it + 2, (it + 2) % 3);

        const __half* sA = AsP(buf);
        const __half* sB = BsP(buf);
#pragma unroll
        for (int kk = 0; kk < 32; kk += 16) {
            if constexpr (B_COL) {
                wmma::fragment<wmma::matrix_b, 16, 16, 16, __half, wmma::col_major> b[4];
#pragma unroll
                for (int nt = 0; nt < 4; nt++)
                    wmma::load_matrix_sync(b[nt], &sB[(wn * 64 + nt * 16) * 40 + kk], 40);
#pragma unroll
                for (int mt = 0; mt < 4; mt++) {
                    wmma::fragment<wmma::matrix_a, 16, 16, 16, __half, wmma::row_major> a;
                    wmma::load_matrix_sync(a, &sA[(wm * 64 + mt * 16) * LDA + kk], LDA);
#pragma unroll
                    for (int nt = 0; nt < 4; nt++)
                        wmma::mma_sync(acc[mt][nt], a, b[nt], acc[mt][nt]);
                }
            } else {
                wmma::fragment<wmma::matrix_b, 16, 16, 16, __half, wmma::row_major> b[4];
#pragma unroll
                for (int nt = 0; nt < 4; nt++)
                    wmma::load_matrix_sync(b[nt], &sB[kk * 136 + wn * 64 + nt * 16], 136);
#pragma unroll
                for (int mt = 0; mt < 4; mt++) {
                    wmma::fragment<wmma::matrix_a, 16, 16, 16, __half, wmma::row_major> a;
                    wmma::load_matrix_sync(a, &sA[(wm * 64 + mt * 16) * LDA + kk], LDA);
#pragma unroll
                    for (int nt = 0; nt < 4; nt++)
                        wmma::mma_sync(acc[mt][nt], a, b[nt], acc[mt][nt]);
                }
            }
        }
    }

    // ---------------- epilogue (per-warp staging; aliases stage 0) ----------------
    __syncthreads();   // all compute done before overwriting stage smem
    float* epbuf = (float*)dsm + w * 320;   // 4 warps x 16x20 floats = 5120 B

    const int r  = lane >> 1;
    const int cb = (lane & 1) * 8;
#pragma unroll
    for (int mt = 0; mt < 4; mt++) {
        const size_t gr = gm0 + wm * 64 + mt * 16 + r;
#pragma unroll
        for (int nt = 0; nt < 4; nt++) {
            wmma::store_matrix_sync(epbuf, acc[mt][nt], 20, wmma::mem_row_major);
            __syncwarp();
            const size_t gc = gn0 + wn * 64 + nt * 16 + cb;
            float v[8];
#pragma unroll
            for (int e = 0; e < 8; e++) v[e] = epbuf[r * 20 + cb + e];

            if constexpr (MODE == 0) {
                __half2 hh[4], ll[4];
#pragma unroll
                for (int e = 0; e < 4; e++) {
                    __half h0 = __float2half_rn(v[e * 2]);
                    __half h1 = __float2half_rn(v[e * 2 + 1]);
                    hh[e] = __halves2half2(h0, h1);
                    ll[e] = __halves2half2(
                        __float2half_rn(v[e * 2]     - __half2float(h0)),
                        __float2half_rn(v[e * 2 + 1] - __half2float(h1)));
                }
                size_t base = gr * KCAT + gc;
                *(uint4*)(g_Acat + base)             = *(uint4*)hh;
                *(uint4*)(g_Acat + base + D_EMB)     = *(uint4*)ll;
                *(uint4*)(g_Acat + base + 2 * D_EMB) = *(uint4*)hh;
            } else if constexpr (MODE == 1) {
                const float* prow = aux + gr * (size_t)N_CELLS + gc;
                float4 p0 = __ldcs((const float4*)prow);
                float4 p1 = __ldcs((const float4*)(prow + 4));
                float pv[8] = {p0.x, p0.y, p0.z, p0.w, p1.x, p1.y, p1.z, p1.w};
                __half2 o[4];
#pragma unroll
                for (int e = 0; e < 4; e++) {
                    float s0 = gate_fn(pv[e * 2],     v[e * 2]);
                    float s1 = gate_fn(pv[e * 2 + 1], v[e * 2 + 1]);
                    o[e] = __floats2half2_rn(s0, s1);
                }
                *(uint4*)(g_gated + gr * (size_t)N_CELLS + gc) = *(uint4*)o;
            } else if constexpr (MODE == 2) {
                __half2 o[4];
#pragma unroll
                for (int e = 0; e < 4; e++)
                    o[e] = __floats2half2_rn(v[e * 2], v[e * 2 + 1]);
                *(uint4*)(g_M1h + gr * D_GENE + gc) = *(uint4*)o;
            } else {
                float4 o0 = make_float4(v[0] * (1.0f / 1024.0f), v[1] * (1.0f / 1024.0f),
                                        v[2] * (1.0f / 1024.0f), v[3] * (1.0f / 1024.0f));
                float4 o1 = make_float4(v[4] * (1.0f / 1024.0f), v[5] * (1.0f / 1024.0f),
                                        v[6] * (1.0f / 1024.0f), v[7] * (1.0f / 1024.0f));
                *(float4*)(outf + gr * D_GENE + gc)     = o0;
                *(float4*)(outf + gr * D_GENE + gc + 4) = o1;
            }
            __syncwarp();
        }
    }
}

// ---------------- launch ----------------
extern "C" void kernel_launch(void* const* d_in, const int* in_sizes, int n_in,
                              void* d_out, int out_size) {
    const float* expr = (const float*)d_in[0];
    const float* enc  = (const float*)d_in[1];
    const float* pd   = (const float*)d_in[2];
    const float* T    = (const float*)d_in[3];
    const float* gr   = (const float*)d_in[4];
    float* out = (float*)d_out;

    cudaFuncSetAttribute(gemm_wmma10<0>, cudaFuncAttributeMaxDynamicSharedMemorySize, DSMEM_B);
    cudaFuncSetAttribute(gemm_wmma10<1>, cudaFuncAttributeMaxDynamicSharedMemorySize, DSMEM_B);
    cudaFuncSetAttribute(gemm_wmma10<2>, cudaFuncAttributeMaxDynamicSharedMemorySize, DSMEM_B);
    cudaFuncSetAttribute(gemm_wmma10<3>, cudaFuncAttributeMaxDynamicSharedMemorySize, DSMEM_B);

    // Order chosen so the 4th launch (ncu capture slot) is the dominant GEMM1.
    k_cvt_enc<<<(N_CELLS * D_EMB) / 256, 256>>>(enc);
    k_cvt_T<<<(D_EMB * D_EMB) / 256, 256>>>(T);
    gemm_wmma10<0><<<dim3(D_EMB / 128,  N_CELLS / 128), 128, DSMEM_B>>>(nullptr, nullptr);
    gemm_wmma10<1><<<dim3(N_CELLS / 128, N_CELLS / 128), 128, DSMEM_B>>>(pd, nullptr);
    k_cvt_expr<<<(N_CELLS * D_GENE) / 256, 256>>>(expr);
    k_cvt_gr<<<(D_GENE * D_GENE) / 256, 256>>>(gr);
    gemm_wmma10<2><<<dim3(D_GENE / 128, N_CELLS / 128), 128, DSMEM_B>>>(nullptr, nullptr);
    gemm_wmma10<3><<<dim3(D_GENE / 128, N_CELLS / 128), 128, DSMEM_B>>>(nullptr, out);
}